// round 3
// baseline (speedup 1.0000x reference)
#include <cuda_runtime.h>
#include <cuda_bf16.h>

// CorrelationLayer: out[b,d,h,w] = (1/sqrt(C)) * sum_c x1[b,c,h,w] * x2pad[b,c,h+di,w+dj]
// 80 displacements ((di,dj) in [-4,4]^2 minus (0,0)). B=8, C=128, H=128, W=192, fp32.
// v3: 8 pixels/thread + packed fma.rn.f32x2 (FFMA2) + cp.async double buffering.

#define CC   128
#define HH   128
#define WW   192
#define BB   8
#define PW   64    // pixel tile width per block
#define PH   2     // pixel tile height per block
#define CHS  8     // channels per smem stage
#define TX   8     // threads along x (each covers 8 pixels)
#define NDI  9     // displacement rows, split across threadIdx.y
#define NTHREADS (TX * NDI * PH)         // 144
#define NSTAGES  (CC / CHS)              // 16
#define HALO_H   (PH + 8)                // 10
#define HALO_W   (PW + 8)                // 72
#define S1_ELEMS (CHS * PH * PW)         // 1024 floats
#define S2_ELEMS (CHS * HALO_H * HALO_W) // 5760 floats
#define X1_SLOTS 2                       // 256 float4 / 144 thr
#define X2_SLOTS 10                      // 1440 float4 / 144 thr

__device__ __forceinline__ unsigned smem_u32(const void* p) {
    return (unsigned)__cvta_generic_to_shared(p);
}
__device__ __forceinline__ void cp16(unsigned dst, const float* src) {
    asm volatile("cp.async.cg.shared.global [%0], [%1], 16;\n" :: "r"(dst), "l"(src));
}
__device__ __forceinline__ void cp_commit() {
    asm volatile("cp.async.commit_group;\n" ::: "memory");
}
template <int N> __device__ __forceinline__ void cp_wait() {
    asm volatile("cp.async.wait_group %0;\n" :: "n"(N) : "memory");
}
__device__ __forceinline__ unsigned long long pk2(float lo, float hi) {
    unsigned long long r;
    asm("mov.b64 %0, {%1, %2};" : "=l"(r) : "f"(lo), "f"(hi));
    return r;
}
__device__ __forceinline__ void fma2(unsigned long long& d,
                                     unsigned long long a, unsigned long long b) {
    asm("fma.rn.f32x2 %0, %1, %2, %0;" : "+l"(d) : "l"(a), "l"(b));
}
__device__ __forceinline__ void unpk2(float& lo, float& hi, unsigned long long v) {
    asm("mov.b64 {%0, %1}, %2;" : "=f"(lo), "=f"(hi) : "l"(v));
}

__global__ __launch_bounds__(NTHREADS, 3)
void corr_kernel(const float* __restrict__ x1,
                 const float* __restrict__ x2,
                 float* __restrict__ out)
{
    __shared__ __align__(16) float s1[2][CHS][PH][PW];
    __shared__ __align__(16) float s2[2][CHS][HALO_H][HALO_W];

    const int tx  = threadIdx.x;   // 0..7
    const int diI = threadIdx.y;   // 0..8
    const int pz  = threadIdx.z;   // 0..1
    const int tid = tx + TX * (diI + NDI * pz);

    const int w0 = blockIdx.x * PW;
    const int h0 = blockIdx.y * PH;
    const int b  = blockIdx.z;

    // Zero both s2 buffers once: OOB halo entries stay 0 forever.
    {
        float4 z = make_float4(0.f, 0.f, 0.f, 0.f);
        float4* p = (float4*)&s2[0][0][0][0];
        for (int i = tid; i < 2 * S2_ELEMS / 4; i += NTHREADS) p[i] = z;
    }

    // ---- hoisted load-slot setup (loop-invariant across stages) ----
    // x1: 256 float4 over 144 threads -> 2 slots
    const float* g1[X1_SLOTS];
    unsigned     s1off[X1_SLOTS];
    bool         h1[X1_SLOTS];
    #pragma unroll
    for (int s = 0; s < X1_SLOTS; s++) {
        int i = tid + NTHREADS * s;
        h1[s] = (i < S1_ELEMS / 4);
        int ii = h1[s] ? i : 0;
        int ch = ii >> 5, r = (ii >> 4) & 1, c4 = ii & 15;
        g1[s]    = x1 + (((size_t)(b * CC + ch) * HH + (h0 + r)) * WW) + w0 + 4 * c4;
        s1off[s] = smem_u32(&s1[0][ch][r][4 * c4]);
    }
    // x2: 1440 float4 over 144 threads -> 10 slots
    const float* g2[X2_SLOTS];
    unsigned     s2off[X2_SLOTS];
    bool         pr[X2_SLOTS];
    #pragma unroll
    for (int s = 0; s < X2_SLOTS; s++) {
        int i   = tid + NTHREADS * s;
        int ch  = i / 180;            // 180 float4 per channel (10 rows * 18)
        int rem = i - ch * 180;
        int r   = rem / 18;
        int c4  = rem - r * 18;
        int hr  = h0 - 4 + r;
        int wc  = w0 - 4 + 4 * c4;
        pr[s] = (hr >= 0) && (hr < HH) && (wc >= 0) && (wc < WW);
        int hrc = pr[s] ? hr : 0;
        int wcc = pr[s] ? wc : 0;
        g2[s]    = x2 + (((size_t)(b * CC + ch) * HH + hrc) * WW) + wcc;
        s2off[s] = smem_u32(&s2[0][ch][r][4 * c4]);
    }

    const size_t gstep = (size_t)CHS * HH * WW;

    unsigned long long acc[9][4];     // 9 dj x 4 pixel-pairs (8 pixels)
    #pragma unroll
    for (int j = 0; j < 9; j++)
        #pragma unroll
        for (int k = 0; k < 4; k++) acc[j][k] = 0ULL;

    const int r2 = pz + diI;

    // ---- prologue: stage 0 into buffer 0 ----
    #pragma unroll
    for (int s = 0; s < X1_SLOTS; s++) if (h1[s]) cp16(s1off[s], g1[s]);
    #pragma unroll
    for (int s = 0; s < X2_SLOTS; s++) if (pr[s]) cp16(s2off[s], g2[s]);
    cp_commit();

    #pragma unroll 1
    for (int st = 0; st < NSTAGES; st++) {
        const int bb = st & 1;
        if (st + 1 < NSTAGES) {
            const unsigned bofs1 = (bb ^ 1) * (S1_ELEMS * 4);
            const unsigned bofs2 = (bb ^ 1) * (S2_ELEMS * 4);
            #pragma unroll
            for (int s = 0; s < X1_SLOTS; s++) {
                g1[s] += gstep;
                if (h1[s]) cp16(s1off[s] + bofs1, g1[s]);
            }
            #pragma unroll
            for (int s = 0; s < X2_SLOTS; s++) {
                g2[s] += gstep;
                if (pr[s]) cp16(s2off[s] + bofs2, g2[s]);
            }
            cp_commit();
            cp_wait<1>();
        } else {
            cp_wait<0>();
        }
        __syncthreads();

        const float* p1 = &s1[bb][0][pz][8 * tx];
        const float* p2 = &s2[bb][0][r2][8 * tx];
        #pragma unroll
        for (int ch = 0; ch < CHS; ch++) {
            // x1: 8 pixels
            float4 a0 = *(const float4*)(p1 + ch * (PH * PW));
            float4 a1 = *(const float4*)(p1 + ch * (PH * PW) + 4);
            // x2: sliding window of 16 values
            float4 t0 = *(const float4*)(p2 + ch * (HALO_H * HALO_W));
            float4 t1 = *(const float4*)(p2 + ch * (HALO_H * HALO_W) + 4);
            float4 t2 = *(const float4*)(p2 + ch * (HALO_H * HALO_W) + 8);
            float4 t3 = *(const float4*)(p2 + ch * (HALO_H * HALO_W) + 12);
            float v[16] = {t0.x, t0.y, t0.z, t0.w, t1.x, t1.y, t1.z, t1.w,
                           t2.x, t2.y, t2.z, t2.w, t3.x, t3.y, t3.z, t3.w};

            unsigned long long A[4];
            A[0] = pk2(a0.x, a0.y); A[1] = pk2(a0.z, a0.w);
            A[2] = pk2(a1.x, a1.y); A[3] = pk2(a1.z, a1.w);

            unsigned long long P[15];
            #pragma unroll
            for (int i = 0; i < 15; i++) P[i] = pk2(v[i], v[i + 1]);

            #pragma unroll
            for (int j = 0; j < 9; j++)
                #pragma unroll
                for (int kp = 0; kp < 4; kp++)
                    fma2(acc[j][kp], A[kp], P[j + 2 * kp]);
        }
        __syncthreads();
    }

    // ---- epilogue: scale + store (skip center displacement) ----
    const float scale = 0.08838834764831845f;  // 1/sqrt(128)
    const int hh = h0 + pz;
    #pragma unroll
    for (int j = 0; j < 9; j++) {
        int lin = diI * 9 + j;
        if (lin == 40) continue;               // (0,0)
        int d = lin - (lin > 40 ? 1 : 0);
        float o[8];
        #pragma unroll
        for (int kp = 0; kp < 4; kp++) {
            float lo, hi;
            unpk2(lo, hi, acc[j][kp]);
            o[2 * kp]     = lo * scale;
            o[2 * kp + 1] = hi * scale;
        }
        float* dst = &out[(((size_t)(b * 80 + d) * HH + hh) * WW) + w0 + 8 * tx];
        *(float4*)dst       = make_float4(o[0], o[1], o[2], o[3]);
        *(float4*)(dst + 4) = make_float4(o[4], o[5], o[6], o[7]);
    }
}

extern "C" void kernel_launch(void* const* d_in, const int* in_sizes, int n_in,
                              void* d_out, int out_size)
{
    const float* x1 = (const float*)d_in[0];
    const float* x2 = (const float*)d_in[1];
    float* out = (float*)d_out;

    dim3 grid(WW / PW, HH / PH, BB);   // (3, 64, 8)
    dim3 block(TX, NDI, PH);           // (8, 9, 2) = 144 threads
    corr_kernel<<<grid, block>>>(x1, x2, out);
}

// round 4
// speedup vs baseline: 1.3864x; 1.3864x over previous
#include <cuda_runtime.h>
#include <cuda_bf16.h>

// CorrelationLayer: out[b,d,h,w] = (1/sqrt(C)) * sum_c x1[b,c,h,w] * x2pad[b,c,h+di,w+dj]
// 80 displacements ((di,dj) in [-4,4]^2 minus (0,0)). B=8, C=128, H=128, W=192, fp32.
// v4: R2 structure (4 px/thread, scalar FFMA) + 3 blocks/SM + 1 barrier/stage
//     + compressed u32 pointer state.

#define CC   128
#define HH   128
#define WW   192
#define BB   8
#define PW   64    // pixel tile width per block
#define PH   2     // pixel tile height per block
#define CHS  8     // channels per smem stage
#define TX   16    // threads along x (each covers 4 pixels)
#define NDI  9     // displacement rows, split across threadIdx.y
#define NTHREADS (TX * NDI * PH)         // 288
#define NSTAGES  (CC / CHS)              // 16
#define HALO_H   (PH + 8)                // 10
#define HALO_W   (PW + 8)                // 72
#define S1_ELEMS (CHS * PH * PW)         // 1024 floats
#define S2_ELEMS (CHS * HALO_H * HALO_W) // 5760 floats
#define X2_SLOTS 5                       // 1440 float4 / 288 threads

__device__ __forceinline__ unsigned smem_u32(const void* p) {
    return (unsigned)__cvta_generic_to_shared(p);
}
__device__ __forceinline__ void cp16(unsigned dst, const char* base, unsigned off) {
    asm volatile("cp.async.cg.shared.global [%0], [%1], 16;\n"
                 :: "r"(dst), "l"(base + off));
}
__device__ __forceinline__ void cp_commit() {
    asm volatile("cp.async.commit_group;\n" ::: "memory");
}
template <int N> __device__ __forceinline__ void cp_wait() {
    asm volatile("cp.async.wait_group %0;\n" :: "n"(N) : "memory");
}

__global__ __launch_bounds__(NTHREADS, 3)
void corr_kernel(const float* __restrict__ x1,
                 const float* __restrict__ x2,
                 float* __restrict__ out)
{
    __shared__ __align__(16) float s1[2][CHS][PH][PW];
    __shared__ __align__(16) float s2[2][CHS][HALO_H][HALO_W];

    const int tx  = threadIdx.x;   // 0..15
    const int diI = threadIdx.y;   // 0..8
    const int pz  = threadIdx.z;   // 0..1
    const int tid = tx + TX * (diI + NDI * pz);

    const int w0 = blockIdx.x * PW;
    const int h0 = blockIdx.y * PH;
    const int b  = blockIdx.z;

    // Zero both s2 buffers once: OOB halo entries stay 0 forever.
    {
        float4 z = make_float4(0.f, 0.f, 0.f, 0.f);
        float4* p = (float4*)&s2[0][0][0][0];
        for (int i = tid; i < 2 * S2_ELEMS / 4; i += NTHREADS) p[i] = z;
    }

    // ---- hoisted load-slot setup (loop-invariant across stages) ----
    // Base pointers (64-bit once) + per-slot u32 BYTE offsets (tensor < 4GB).
    const char* base1 = (const char*)x1;
    const char* base2 = (const char*)x2;

    // x1: one float4 per thread for tid < 256
    unsigned g1off = 0, s1off = 0;
    const bool has1 = (tid < 256);
    if (has1) {
        int ch = tid >> 5, r = (tid >> 4) & 1, c4 = tid & 15;
        g1off = (unsigned)((((b * CC + ch) * HH + (h0 + r)) * WW + w0 + 4 * c4) * 4);
        s1off = smem_u32(&s1[0][ch][r][4 * c4]);
    }
    // x2: 5 float4 slots per thread (1440 float4 / 288 threads)
    unsigned g2off[X2_SLOTS];
    unsigned s2off[X2_SLOTS];
    bool     pr[X2_SLOTS];
    #pragma unroll
    for (int s = 0; s < X2_SLOTS; s++) {
        int i   = tid + NTHREADS * s;
        int ch  = i / 180;            // 180 float4 per channel (10 rows * 18)
        int rem = i - ch * 180;
        int r   = rem / 18;
        int c4  = rem - r * 18;
        int hr  = h0 - 4 + r;
        int wc  = w0 - 4 + 4 * c4;
        // float4 groups are all-in or all-out of the image (w0 % 4 == 0)
        pr[s] = (hr >= 0) && (hr < HH) && (wc >= 0) && (wc < WW);
        int hrc = pr[s] ? hr : 0;
        int wcc = pr[s] ? wc : 0;
        g2off[s] = (unsigned)((((b * CC + ch) * HH + hrc) * WW + wcc) * 4);
        s2off[s] = smem_u32(&s2[0][ch][r][4 * c4]);
    }

    const unsigned gstep = (unsigned)(CHS * HH * WW * 4);  // bytes per channel-stage

    float acc[9][4];
    #pragma unroll
    for (int j = 0; j < 9; j++)
        #pragma unroll
        for (int k = 0; k < 4; k++) acc[j][k] = 0.0f;

    const int r2 = pz + diI;

    __syncthreads();   // zero-init of s2 complete before any cp.async lands

    // ---- prologue: stage 0 into buffer 0 ----
    if (has1) cp16(s1off, base1, g1off);
    #pragma unroll
    for (int s = 0; s < X2_SLOTS; s++)
        if (pr[s]) cp16(s2off[s], base2, g2off[s]);
    cp_commit();

    #pragma unroll 1
    for (int st = 0; st < NSTAGES; st++) {
        const int bb = st & 1;

        cp_wait<0>();       // my copies for stage st have landed
        __syncthreads();    // everyone's stage-st copies landed AND everyone
                            // finished computing stage st-1 (safe to refill buf^1)

        if (st + 1 < NSTAGES) {
            const unsigned bofs1 = (bb ^ 1) * (S1_ELEMS * 4);
            const unsigned bofs2 = (bb ^ 1) * (S2_ELEMS * 4);
            if (has1) { g1off += gstep; cp16(s1off + bofs1, base1, g1off); }
            #pragma unroll
            for (int s = 0; s < X2_SLOTS; s++) {
                g2off[s] += gstep;
                if (pr[s]) cp16(s2off[s] + bofs2, base2, g2off[s]);
            }
            cp_commit();
        }

        const float* p1 = &s1[bb][0][pz][4 * tx];
        const float* p2 = &s2[bb][0][r2][4 * tx];
        #pragma unroll
        for (int ch = 0; ch < CHS; ch++) {
            float4 a4 = *(const float4*)(p1 + ch * (PH * PW));
            float4 t0 = *(const float4*)(p2 + ch * (HALO_H * HALO_W));
            float4 t1 = *(const float4*)(p2 + ch * (HALO_H * HALO_W) + 4);
            float4 t2 = *(const float4*)(p2 + ch * (HALO_H * HALO_W) + 8);
            float a[4]  = {a4.x, a4.y, a4.z, a4.w};
            float v[12] = {t0.x, t0.y, t0.z, t0.w,
                           t1.x, t1.y, t1.z, t1.w,
                           t2.x, t2.y, t2.z, t2.w};
            #pragma unroll
            for (int j = 0; j < 9; j++)
                #pragma unroll
                for (int k = 0; k < 4; k++)
                    acc[j][k] = fmaf(a[k], v[j + k], acc[j][k]);
        }
    }

    // ---- epilogue: scale + store (skip center displacement) ----
    const float scale = 0.08838834764831845f;  // 1/sqrt(128)
    const int hh = h0 + pz;
    #pragma unroll
    for (int j = 0; j < 9; j++) {
        int lin = diI * 9 + j;
        if (lin == 40) continue;               // (0,0)
        int d = lin - (lin > 40 ? 1 : 0);
        float4 o;
        o.x = acc[j][0] * scale;
        o.y = acc[j][1] * scale;
        o.z = acc[j][2] * scale;
        o.w = acc[j][3] * scale;
        *(float4*)&out[(((size_t)(b * 80 + d) * HH + hh) * WW) + w0 + 4 * tx] = o;
    }
}

extern "C" void kernel_launch(void* const* d_in, const int* in_sizes, int n_in,
                              void* d_out, int out_size)
{
    const float* x1 = (const float*)d_in[0];
    const float* x2 = (const float*)d_in[1];
    float* out = (float*)d_out;

    dim3 grid(WW / PW, HH / PH, BB);   // (3, 64, 8)
    dim3 block(TX, NDI, PH);           // (16, 9, 2) = 288 threads
    corr_kernel<<<grid, block>>>(x1, x2, out);
}

// round 5
// speedup vs baseline: 1.4229x; 1.0263x over previous
#include <cuda_runtime.h>
#include <cuda_bf16.h>

// CorrelationLayer: out[b,d,h,w] = (1/sqrt(C)) * sum_c x1[b,c,h,w] * x2pad[b,c,h+di,w+dj]
// 80 displacements ((di,dj) in [-4,4]^2 minus (0,0)). B=8, C=128, H=128, W=192, fp32.
// v5: diagonal (pz,diI) warp pairing so both 16-lane halves of a warp read the
//     SAME x2 halo row -> smem broadcast dedup halves x2 LDS crossbar cost.

#define CC   128
#define HH   128
#define WW   192
#define BB   8
#define PW   64    // pixel tile width per block
#define PH   2     // pixel tile height per block
#define CHS  8     // channels per smem stage
#define TX   16    // threads along x (each covers 4 pixels)
#define NDI  9
#define NTHREADS (TX * NDI * PH)         // 288
#define NSTAGES  (CC / CHS)              // 16
#define HALO_H   (PH + 8)                // 10
#define HALO_W   (PW + 8)                // 72
#define S1_ELEMS (CHS * PH * PW)         // 1024 floats
#define S2_ELEMS (CHS * HALO_H * HALO_W) // 5760 floats
#define X2_SLOTS 5                       // 1440 float4 / 288 threads

__device__ __forceinline__ unsigned smem_u32(const void* p) {
    return (unsigned)__cvta_generic_to_shared(p);
}
__device__ __forceinline__ void cp16(unsigned dst, const char* base, unsigned off) {
    asm volatile("cp.async.cg.shared.global [%0], [%1], 16;\n"
                 :: "r"(dst), "l"(base + off));
}
__device__ __forceinline__ void cp_commit() {
    asm volatile("cp.async.commit_group;\n" ::: "memory");
}
template <int N> __device__ __forceinline__ void cp_wait() {
    asm volatile("cp.async.wait_group %0;\n" :: "n"(N) : "memory");
}

__global__ __launch_bounds__(NTHREADS, 3)
void corr_kernel(const float* __restrict__ x1,
                 const float* __restrict__ x2,
                 float* __restrict__ out)
{
    __shared__ __align__(16) float s1[2][CHS][PH][PW];
    __shared__ __align__(16) float s2[2][CHS][HALO_H][HALO_W];

    const int tid = threadIdx.x;           // 0..287 (flat)
    const int tx  = tid & 15;              // 0..15
    const int s   = (tid >> 4) & 1;        // half-warp id
    const int w   = tid >> 5;              // warp id 0..8

    // Diagonal pairing: halves of a warp share r2 = pz + diI (= w, except wrap warp 0).
    const int pz  = s;
    const int diI = s ? (w + 8) % 9 : w;   // s=0 -> w ; s=1 -> w-1 mod 9

    const int w0 = blockIdx.x * PW;
    const int h0 = blockIdx.y * PH;
    const int b  = blockIdx.z;

    // Zero both s2 buffers once: OOB halo entries stay 0 forever.
    {
        float4 z = make_float4(0.f, 0.f, 0.f, 0.f);
        float4* p = (float4*)&s2[0][0][0][0];
        for (int i = tid; i < 2 * S2_ELEMS / 4; i += NTHREADS) p[i] = z;
    }

    // ---- hoisted load-slot setup (loop-invariant across stages) ----
    const char* base1 = (const char*)x1;
    const char* base2 = (const char*)x2;

    // x1: one float4 per thread for tid < 256
    unsigned g1off = 0, s1off = 0;
    const bool has1 = (tid < 256);
    if (has1) {
        int ch = tid >> 5, r = (tid >> 4) & 1, c4 = tid & 15;
        g1off = (unsigned)((((b * CC + ch) * HH + (h0 + r)) * WW + w0 + 4 * c4) * 4);
        s1off = smem_u32(&s1[0][ch][r][4 * c4]);
    }
    // x2: 5 float4 slots per thread (1440 float4 / 288 threads)
    unsigned g2off[X2_SLOTS];
    unsigned s2off[X2_SLOTS];
    bool     pr[X2_SLOTS];
    #pragma unroll
    for (int sl = 0; sl < X2_SLOTS; sl++) {
        int i   = tid + NTHREADS * sl;
        int ch  = i / 180;            // 180 float4 per channel (10 rows * 18)
        int rem = i - ch * 180;
        int r   = rem / 18;
        int c4  = rem - r * 18;
        int hr  = h0 - 4 + r;
        int wc  = w0 - 4 + 4 * c4;
        pr[sl] = (hr >= 0) && (hr < HH) && (wc >= 0) && (wc < WW);
        int hrc = pr[sl] ? hr : 0;
        int wcc = pr[sl] ? wc : 0;
        g2off[sl] = (unsigned)((((b * CC + ch) * HH + hrc) * WW + wcc) * 4);
        s2off[sl] = smem_u32(&s2[0][ch][r][4 * c4]);
    }

    const unsigned gstep = (unsigned)(CHS * HH * WW * 4);

    float acc[9][4];
    #pragma unroll
    for (int j = 0; j < 9; j++)
        #pragma unroll
        for (int k = 0; k < 4; k++) acc[j][k] = 0.0f;

    const int r2 = pz + diI;          // = w for 17 of 18 combos

    __syncthreads();   // zero-init of s2 complete before any cp.async lands

    // ---- prologue: stage 0 into buffer 0 ----
    if (has1) cp16(s1off, base1, g1off);
    #pragma unroll
    for (int sl = 0; sl < X2_SLOTS; sl++)
        if (pr[sl]) cp16(s2off[sl], base2, g2off[sl]);
    cp_commit();

    #pragma unroll 1
    for (int st = 0; st < NSTAGES; st++) {
        const int bb = st & 1;

        cp_wait<0>();
        __syncthreads();    // stage-st data landed AND stage st-1 consumed

        if (st + 1 < NSTAGES) {
            const unsigned bofs1 = (bb ^ 1) * (S1_ELEMS * 4);
            const unsigned bofs2 = (bb ^ 1) * (S2_ELEMS * 4);
            if (has1) { g1off += gstep; cp16(s1off + bofs1, base1, g1off); }
            #pragma unroll
            for (int sl = 0; sl < X2_SLOTS; sl++) {
                g2off[sl] += gstep;
                if (pr[sl]) cp16(s2off[sl] + bofs2, base2, g2off[sl]);
            }
            cp_commit();
        }

        const float* p1 = &s1[bb][0][pz][4 * tx];
        const float* p2 = &s2[bb][0][r2][4 * tx];
        #pragma unroll
        for (int ch = 0; ch < CHS; ch++) {
            float4 a4 = *(const float4*)(p1 + ch * (PH * PW));
            float4 t0 = *(const float4*)(p2 + ch * (HALO_H * HALO_W));
            float4 t1 = *(const float4*)(p2 + ch * (HALO_H * HALO_W) + 4);
            float4 t2 = *(const float4*)(p2 + ch * (HALO_H * HALO_W) + 8);
            float a[4]  = {a4.x, a4.y, a4.z, a4.w};
            float v[12] = {t0.x, t0.y, t0.z, t0.w,
                           t1.x, t1.y, t1.z, t1.w,
                           t2.x, t2.y, t2.z, t2.w};
            #pragma unroll
            for (int j = 0; j < 9; j++)
                #pragma unroll
                for (int k = 0; k < 4; k++)
                    acc[j][k] = fmaf(a[k], v[j + k], acc[j][k]);
        }
    }

    // ---- epilogue: scale + store (skip center displacement) ----
    const float scale = 0.08838834764831845f;  // 1/sqrt(128)
    const int hh = h0 + pz;
    #pragma unroll
    for (int j = 0; j < 9; j++) {
        int lin = diI * 9 + j;
        if (lin == 40) continue;               // (0,0)
        int d = lin - (lin > 40 ? 1 : 0);
        float4 o;
        o.x = acc[j][0] * scale;
        o.y = acc[j][1] * scale;
        o.z = acc[j][2] * scale;
        o.w = acc[j][3] * scale;
        *(float4*)&out[(((size_t)(b * 80 + d) * HH + hh) * WW) + w0 + 4 * tx] = o;
    }
}

extern "C" void kernel_launch(void* const* d_in, const int* in_sizes, int n_in,
                              void* d_out, int out_size)
{
    const float* x1 = (const float*)d_in[0];
    const float* x2 = (const float*)d_in[1];
    float* out = (float*)d_out;

    dim3 grid(WW / PW, HH / PH, BB);   // (3, 64, 8)
    dim3 block(NTHREADS, 1, 1);        // flat 288, warp mapping done in-kernel
    corr_kernel<<<grid, block>>>(x1, x2, out);
}